// round 2
// baseline (speedup 1.0000x reference)
#include <cuda_runtime.h>

#define HH 256
#define WW 256
#define HWSZ 65536
#define BB 2
#define CC 96
#define CP 100   // padded channel stride for NHWC splat accumulator (16B aligned)

// ---------------- scratch (static device globals; no allocations) ----------------
__device__ __align__(16) float g_m  [2 * BB * HWSZ];        // L1 warp-error metric (mL, mR)
__device__ __align__(16) float g_em [2 * BB * HWSZ];        // exp(clip(alpha * metric_net))
__device__ __align__(16) float g_x1 [(size_t)BB * 64 * HWSZ];
__device__ __align__(16) float g_x2 [(size_t)BB * 64 * HWSZ];
__device__ __align__(16) float g_acc[(size_t)2 * BB * HWSZ * CP]; // NHWC splat accum (96 vals + weight)
__device__ __align__(16) float g_w1t[97 * 576];             // weights transposed to [cin][k][cout]
__device__ __align__(16) float g_w2t[64 * 576];

// ---------------- weight transpose: OIHW -> [cin][k][cout] ----------------
__global__ void transpose_w1_kernel(const float* __restrict__ w) {
    int i = blockIdx.x * 256 + threadIdx.x;
    if (i < 97 * 576) {
        int cin = i / 576, r = i % 576, k = r >> 6, co = r & 63;
        g_w1t[i] = w[((size_t)co * 97 + cin) * 9 + k];
    }
}
__global__ void transpose_w2_kernel(const float* __restrict__ w) {
    int i = blockIdx.x * 256 + threadIdx.x;
    if (i < 64 * 576) {
        int cin = i / 576, r = i % 576, k = r >> 6, co = r & 63;
        g_w2t[i] = w[((size_t)co * 64 + cin) * 9 + k];
    }
}

// ---------------- backwarp + channel-mean |A - warp(B)| ----------------
__global__ void warp_metric_kernel(const float* __restrict__ biflow,
                                   const float* __restrict__ fA,
                                   const float* __restrict__ fB,
                                   int branch) {
    int pix = blockIdx.x * blockDim.x + threadIdx.x;
    int b = blockIdx.y;
    int x = pix & (WW - 1);
    int y = pix >> 8;
    const float* bf = biflow + ((size_t)b * 4 + branch * 2) * HWSZ + pix;
    float tx = (float)x + bf[0] * 0.125f;
    float ty = (float)y + bf[HWSZ] * 0.125f;
    float x0f = floorf(tx), y0f = floorf(ty);
    float ax = tx - x0f, ay = ty - y0f;
    int x0 = (int)x0f, y0 = (int)y0f;
    float w[4] = {(1.f - ax) * (1.f - ay), ax * (1.f - ay), (1.f - ax) * ay, ax * ay};
    int off[4];
    float wv[4];
#pragma unroll
    for (int i = 0; i < 4; i++) {
        int xi = x0 + (i & 1), yi = y0 + (i >> 1);
        bool v = (xi >= 0 && xi < WW && yi >= 0 && yi < HH);
        wv[i] = v ? w[i] : 0.f;
        int xc = min(max(xi, 0), WW - 1);
        int yc = min(max(yi, 0), HH - 1);
        off[i] = yc * WW + xc;
    }
    const float* A  = fA + (size_t)b * CC * HWSZ + pix;
    const float* Bp = fB + (size_t)b * CC * HWSZ;
    float s = 0.f;
#pragma unroll 4
    for (int c = 0; c < CC; c++) {
        float v = wv[0] * Bp[off[0]] + wv[1] * Bp[off[1]] +
                  wv[2] * Bp[off[2]] + wv[3] * Bp[off[3]];
        s += fabsf(A[0] - v);
        A += HWSZ; Bp += HWSZ;
    }
    g_m[(size_t)(branch * BB + b) * HWSZ + pix] = s * (1.f / 96.f);
}

// ---------------- tiled 3x3 conv, 64 out channels in registers, leaky 0.1 ----------------
template <int CIN, int STAGE>
__global__ __launch_bounds__(256) void conv_kernel(const float* __restrict__ feat,
                                                   const float* __restrict__ bias,
                                                   int branch) {
    __shared__ float tile[10][34];
    __shared__ __align__(16) float ws[576];
    __shared__ float bs[64];
    int b = blockIdx.z;
    int bx = blockIdx.x * 32, by = blockIdx.y * 8;
    int tx = threadIdx.x, ty = threadIdx.y;
    int tid = ty * 32 + tx;
    if (tid < 64) bs[tid] = bias[tid];
    float acc[64];
#pragma unroll
    for (int i = 0; i < 64; i++) acc[i] = 0.f;
    const float* wt = (STAGE == 1) ? g_w1t : g_w2t;
    for (int cin = 0; cin < CIN; cin++) {
        const float* src;
        if (STAGE == 1)
            src = (cin == 0) ? (g_m + (size_t)(branch * BB + b) * HWSZ)
                             : (feat + ((size_t)b * CC + (cin - 1)) * HWSZ);
        else
            src = g_x1 + ((size_t)b * 64 + cin) * HWSZ;
        for (int i = tid; i < 340; i += 256) {
            int r = i / 34, c = i % 34;
            int gy = by + r - 1, gx = bx + c - 1;
            tile[r][c] = (gy >= 0 && gy < HH && gx >= 0 && gx < WW) ? src[gy * WW + gx] : 0.f;
        }
        {
            const float4* wsrc = (const float4*)(wt + (size_t)cin * 576);
            float4* wdst = (float4*)ws;
            for (int i = tid; i < 144; i += 256) wdst[i] = wsrc[i];
        }
        __syncthreads();
        float inv[9];
#pragma unroll
        for (int ky = 0; ky < 3; ky++)
#pragma unroll
            for (int kx = 0; kx < 3; kx++)
                inv[ky * 3 + kx] = tile[ty + ky][tx + kx];
#pragma unroll
        for (int k = 0; k < 9; k++) {
            float v = inv[k];
            const float4* w4 = (const float4*)(ws + k * 64);
#pragma unroll
            for (int j = 0; j < 16; j++) {
                float4 ww = w4[j];
                acc[4 * j + 0] += v * ww.x;
                acc[4 * j + 1] += v * ww.y;
                acc[4 * j + 2] += v * ww.z;
                acc[4 * j + 3] += v * ww.w;
            }
        }
        __syncthreads();
    }
    float* outp = (STAGE == 1) ? g_x1 : g_x2;
    int pix = (by + ty) * WW + bx + tx;
#pragma unroll
    for (int co = 0; co < 64; co++) {
        float r = acc[co] + bs[co];
        r = r > 0.f ? r : 0.1f * r;
        outp[((size_t)b * 64 + co) * HWSZ + pix] = r;
    }
}

// ---------------- conv3 (64 -> 1) + alpha * clip + exp  ----------------
__global__ __launch_bounds__(256) void conv3_kernel(const float* __restrict__ w3,
                                                    const float* __restrict__ b3,
                                                    const float* __restrict__ alpha,
                                                    int branch) {
    __shared__ float tile[10][34];
    __shared__ float ws[576];
    int b = blockIdx.z;
    int bx = blockIdx.x * 32, by = blockIdx.y * 8;
    int tx = threadIdx.x, ty = threadIdx.y;
    int tid = ty * 32 + tx;
    for (int i = tid; i < 576; i += 256) ws[i] = w3[i];
    float acc = 0.f;
    for (int cin = 0; cin < 64; cin++) {
        const float* src = g_x2 + ((size_t)b * 64 + cin) * HWSZ;
        for (int i = tid; i < 340; i += 256) {
            int r = i / 34, c = i % 34;
            int gy = by + r - 1, gx = bx + c - 1;
            tile[r][c] = (gy >= 0 && gy < HH && gx >= 0 && gx < WW) ? src[gy * WW + gx] : 0.f;
        }
        __syncthreads();
#pragma unroll
        for (int ky = 0; ky < 3; ky++)
#pragma unroll
            for (int kx = 0; kx < 3; kx++)
                acc += tile[ty + ky][tx + kx] * ws[cin * 9 + ky * 3 + kx];
        __syncthreads();
    }
    float v = alpha[0] * (acc + b3[0]);
    v = fminf(fmaxf(v, -20.f), 20.f);
    g_em[(size_t)(branch * BB + b) * HWSZ + (by + ty) * WW + bx + tx] = expf(v);
}

// ---------------- clear splat accumulators (every launch) ----------------
__global__ void clear_kernel() {
    size_t i = (size_t)blockIdx.x * blockDim.x + threadIdx.x;
    size_t n = (size_t)2 * BB * HWSZ * CP / 4;
    if (i < n) ((float4*)g_acc)[i] = make_float4(0.f, 0.f, 0.f, 0.f);
}

// ---------------- softmax splat: thread-per-pixel, NHWC accum, vec4 red atomics ----------------
__device__ __forceinline__ void red_add_v4(float* p, float a, float b, float c, float d) {
    asm volatile("red.global.add.v4.f32 [%0], {%1, %2, %3, %4};"
                 :: "l"(p), "f"(a), "f"(b), "f"(c), "f"(d) : "memory");
}

__global__ __launch_bounds__(256) void splat_kernel(const float* __restrict__ biflow,
                                                    const float* __restrict__ fL,
                                                    const float* __restrict__ fR) {
    int pix = blockIdx.x * blockDim.x + threadIdx.x;
    int branch = blockIdx.y >> 1;
    int b = blockIdx.y & 1;
    int x = pix & (WW - 1), y = pix >> 8;
    const float* bf = biflow + ((size_t)b * 4 + branch * 2) * HWSZ + pix;
    float tx = (float)x + bf[0] * 0.125f;
    float ty = (float)y + bf[HWSZ] * 0.125f;
    float x0f = floorf(tx), y0f = floorf(ty);
    float ax = tx - x0f, ay = ty - y0f;
    int x0 = (int)x0f, y0 = (int)y0f;
    float w[4] = {(1.f - ax) * (1.f - ay), ax * (1.f - ay), (1.f - ax) * ay, ax * ay};
    bool ok[4];
    size_t noff[4];
    int nvalid = 0;
#pragma unroll
    for (int i = 0; i < 4; i++) {
        int xi = x0 + (i & 1), yi = y0 + (i >> 1);
        ok[i] = (xi >= 0 && xi < WW && yi >= 0 && yi < HH) && (w[i] != 0.f);
        noff[i] = (size_t)(yi * WW + xi) * CP;
        nvalid += ok[i];
    }
    float m = g_em[(size_t)(branch * BB + b) * HWSZ + pix];
    const float* feat = (branch == 0 ? fL : fR) + (size_t)b * CC * HWSZ + pix;
    float* accb = g_acc + (size_t)(branch * BB + b) * HWSZ * CP;
    if (nvalid) {
#pragma unroll 4
        for (int g = 0; g < 24; g++) {
            float v0 = feat[(size_t)(4 * g + 0) * HWSZ] * m;
            float v1 = feat[(size_t)(4 * g + 1) * HWSZ] * m;
            float v2 = feat[(size_t)(4 * g + 2) * HWSZ] * m;
            float v3 = feat[(size_t)(4 * g + 3) * HWSZ] * m;
#pragma unroll
            for (int i = 0; i < 4; i++)
                if (ok[i])
                    red_add_v4(accb + noff[i] + 4 * g,
                               v0 * w[i], v1 * w[i], v2 * w[i], v3 * w[i]);
        }
#pragma unroll
        for (int i = 0; i < 4; i++)
            if (ok[i]) atomicAdd(accb + noff[i] + 96, m * w[i]);
    }
}

// ---------------- normalize + NHWC -> NCHW transpose ----------------
__global__ __launch_bounds__(256) void normalize_kernel(float* __restrict__ outWL,
                                                        float* __restrict__ outWR) {
    __shared__ float s[32 * CP];
    int bz = blockIdx.y;            // 0..3 : branch*2 + b
    int branch = bz >> 1, b = bz & 1;
    int pix0 = blockIdx.x * 32;
    int tid = threadIdx.x;
    const float* base = g_acc + ((size_t)bz * HWSZ + pix0) * CP;
    for (int i = tid; i < 32 * CP; i += 256) s[i] = base[i];
    __syncthreads();
    float* out = (branch == 0 ? outWL : outWR) + (size_t)b * CC * HWSZ + pix0;
    int tx = tid & 31;
    float inv = 1.f / (s[tx * CP + 96] + 1e-7f);
    for (int c = tid >> 5; c < CC; c += 8)
        out[(size_t)c * HWSZ + tx] = s[tx * CP + c] * inv;
}

// ---------------- 9x9 correlation volume + leaky 0.1 ----------------
__global__ __launch_bounds__(256) void corr_kernel(const float* __restrict__ wl,
                                                   const float* __restrict__ wr,
                                                   float* __restrict__ cost) {
    __shared__ float Lt[8][8][32];
    __shared__ float Rt[8][16][40];
    int b = blockIdx.z;
    int bx = blockIdx.x * 32, by = blockIdx.y * 8;
    int tx = threadIdx.x, ty = threadIdx.y;
    int tid = ty * 32 + tx;
    float acc[81];
#pragma unroll
    for (int d = 0; d < 81; d++) acc[d] = 0.f;
    for (int ch0 = 0; ch0 < CC; ch0 += 8) {
#pragma unroll
        for (int c = 0; c < 8; c++)
            Lt[c][ty][tx] = wl[((size_t)b * CC + ch0 + c) * HWSZ + (by + ty) * WW + bx + tx];
        for (int i = tid; i < 8 * 16 * 40; i += 256) {
            int c = i / 640, rem = i % 640, r = rem / 40, cc = rem % 40;
            int gy = by + r - 4, gx = bx + cc - 4;
            Rt[c][r][cc] = (gy >= 0 && gy < HH && gx >= 0 && gx < WW)
                               ? wr[((size_t)b * CC + ch0 + c) * HWSZ + gy * WW + gx]
                               : 0.f;
        }
        __syncthreads();
#pragma unroll
        for (int c = 0; c < 8; c++) {
            float v = Lt[c][ty][tx];
#pragma unroll
            for (int dy = 0; dy < 9; dy++)
#pragma unroll
                for (int dx = 0; dx < 9; dx++)
                    acc[dy * 9 + dx] += v * Rt[c][ty + dy][tx + dx];
        }
        __syncthreads();
    }
    int pix = (by + ty) * WW + bx + tx;
#pragma unroll
    for (int d = 0; d < 81; d++) {
        float r = acc[d] * (1.f / 96.f);
        r = r > 0.f ? r : 0.1f * r;
        cost[((size_t)b * 81 + d) * HWSZ + pix] = r;
    }
}

// ---------------- launch ----------------
extern "C" void kernel_launch(void* const* d_in, const int* in_sizes, int n_in,
                              void* d_out, int out_size) {
    const float* biflow = (const float*)d_in[0];
    const float* fL     = (const float*)d_in[1];
    const float* fR     = (const float*)d_in[2];
    const float* alpha  = (const float*)d_in[3];
    const float* w1     = (const float*)d_in[4];
    const float* b1     = (const float*)d_in[5];
    const float* w2     = (const float*)d_in[6];
    const float* b2     = (const float*)d_in[7];
    const float* w3     = (const float*)d_in[8];
    const float* b3     = (const float*)d_in[9];
    float* out   = (float*)d_out;
    float* outWL = out;
    float* outWR = out + (size_t)BB * CC * HWSZ;
    float* outC  = out + (size_t)2 * BB * CC * HWSZ;

    transpose_w1_kernel<<<(97 * 576 + 255) / 256, 256>>>(w1);
    transpose_w2_kernel<<<(64 * 576 + 255) / 256, 256>>>(w2);

    // clear accumulators early (overlaps nothing, but independent of convs)
    size_t nclr = (size_t)2 * BB * HWSZ * CP / 4;
    clear_kernel<<<(unsigned)((nclr + 255) / 256), 256>>>();

    dim3 g1(HWSZ / 256, BB);
    warp_metric_kernel<<<g1, 256>>>(biflow, fL, fR, 0);
    warp_metric_kernel<<<g1, 256>>>(biflow, fR, fL, 1);

    dim3 cblk(32, 8), cgrd(WW / 32, HH / 8, BB);
    conv_kernel<97, 1><<<cgrd, cblk>>>(fL, b1, 0);
    conv_kernel<64, 2><<<cgrd, cblk>>>(nullptr, b2, 0);
    conv3_kernel<<<cgrd, cblk>>>(w3, b3, alpha, 0);
    conv_kernel<97, 1><<<cgrd, cblk>>>(fR, b1, 1);
    conv_kernel<64, 2><<<cgrd, cblk>>>(nullptr, b2, 1);
    conv3_kernel<<<cgrd, cblk>>>(w3, b3, alpha, 1);

    dim3 gs(HWSZ / 256, 2 * BB);
    splat_kernel<<<gs, 256>>>(biflow, fL, fR);

    dim3 gn(HWSZ / 32, 2 * BB);
    normalize_kernel<<<gn, 256>>>(outWL, outWR);

    corr_kernel<<<cgrd, cblk>>>(outWL, outWR, outC);
}

// round 5
// speedup vs baseline: 1.1900x; 1.1900x over previous
#include <cuda_runtime.h>

#define HH 256
#define WW 256
#define HWSZ 65536
#define BB 2
#define CC 96
#define CP 100   // padded channel stride for NHWC splat accumulator (16B aligned)

typedef unsigned long long ull;

// ---------------- scratch (static device globals; no allocations) ----------------
__device__ __align__(16) float g_m  [2 * BB * HWSZ];        // L1 warp-error metric
__device__ __align__(16) float g_em [2 * BB * HWSZ];        // exp(clip(alpha * metric_net))
__device__ __align__(16) float g_x1 [(size_t)2 * BB * 64 * HWSZ];   // per-branch
__device__ __align__(16) float g_x2 [(size_t)2 * BB * 64 * HWSZ];   // per-branch
__device__ __align__(16) float g_acc[(size_t)2 * BB * HWSZ * CP];   // NHWC splat accum
__device__ __align__(16) float g_w1t[97 * 576];             // [cin][k][cout]
__device__ __align__(16) float g_w2t[64 * 576];

// ---------------- f32x2 helpers ----------------
__device__ __forceinline__ ull pack2(float lo, float hi) {
    ull r; asm("mov.b64 %0, {%1, %2};" : "=l"(r) : "f"(lo), "f"(hi)); return r;
}
__device__ __forceinline__ void unpack2(ull v, float& lo, float& hi) {
    asm("mov.b64 {%0, %1}, %2;" : "=f"(lo), "=f"(hi) : "l"(v));
}
__device__ __forceinline__ void fma2(ull& d, ull a, ull b) {
    asm("fma.rn.f32x2 %0, %1, %2, %0;" : "+l"(d) : "l"(a), "l"(b));
}

// ---------------- weight transpose: OIHW -> [cin][k][cout] ----------------
__global__ void transpose_w1_kernel(const float* __restrict__ w) {
    int i = blockIdx.x * 256 + threadIdx.x;
    if (i < 97 * 576) {
        int cin = i / 576, r = i % 576, k = r >> 6, co = r & 63;
        g_w1t[i] = w[((size_t)co * 97 + cin) * 9 + k];
    }
}
__global__ void transpose_w2_kernel(const float* __restrict__ w) {
    int i = blockIdx.x * 256 + threadIdx.x;
    if (i < 64 * 576) {
        int cin = i / 576, r = i % 576, k = r >> 6, co = r & 63;
        g_w2t[i] = w[((size_t)co * 64 + cin) * 9 + k];
    }
}

// ---------------- backwarp + channel-mean |A - warp(B)| (both branches in one grid) ----
__global__ __launch_bounds__(256) void warp_metric_kernel(const float* __restrict__ biflow,
                                                          const float* __restrict__ fL,
                                                          const float* __restrict__ fR) {
    int pix = blockIdx.x * blockDim.x + threadIdx.x;
    int b = blockIdx.y;
    int branch = blockIdx.z;
    const float* fA = branch ? fR : fL;
    const float* fB = branch ? fL : fR;
    int x = pix & (WW - 1);
    int y = pix >> 8;
    const float* bf = biflow + ((size_t)b * 4 + branch * 2) * HWSZ + pix;
    float tx = (float)x + bf[0] * 0.125f;
    float ty = (float)y + bf[HWSZ] * 0.125f;
    float x0f = floorf(tx), y0f = floorf(ty);
    float ax = tx - x0f, ay = ty - y0f;
    int x0 = (int)x0f, y0 = (int)y0f;
    float w[4] = {(1.f - ax) * (1.f - ay), ax * (1.f - ay), (1.f - ax) * ay, ax * ay};
    int off[4];
    float wv[4];
#pragma unroll
    for (int i = 0; i < 4; i++) {
        int xi = x0 + (i & 1), yi = y0 + (i >> 1);
        bool v = (xi >= 0 && xi < WW && yi >= 0 && yi < HH);
        wv[i] = v ? w[i] : 0.f;
        int xc = min(max(xi, 0), WW - 1);
        int yc = min(max(yi, 0), HH - 1);
        off[i] = yc * WW + xc;
    }
    const float* A  = fA + (size_t)b * CC * HWSZ + pix;
    const float* Bp = fB + (size_t)b * CC * HWSZ;
    float s = 0.f;
#pragma unroll 8
    for (int c = 0; c < CC; c++) {
        float v = wv[0] * Bp[off[0]] + wv[1] * Bp[off[1]] +
                  wv[2] * Bp[off[2]] + wv[3] * Bp[off[3]];
        s += fabsf(A[0] - v);
        A += HWSZ; Bp += HWSZ;
    }
    g_m[(size_t)(branch * BB + b) * HWSZ + pix] = s * (1.f / 96.f);
}

// ---------------- tiled 3x3 conv via packed f32x2, 64 out channels, leaky 0.1 ----------
// grid.z = branch*BB + b (both branches in one launch)
template <int CIN, int STAGE>
__global__ __launch_bounds__(256, 2) void conv_kernel(const float* __restrict__ fL,
                                                      const float* __restrict__ fR,
                                                      const float* __restrict__ bias) {
    __shared__ float tile[10][34];
    __shared__ __align__(16) float ws[576];
    __shared__ float bs[64];
    int bz = blockIdx.z;
    int branch = bz >> 1, b = bz & 1;
    int bx = blockIdx.x * 32, by = blockIdx.y * 8;
    int tx = threadIdx.x, ty = threadIdx.y;
    int tid = ty * 32 + tx;
    if (tid < 64) bs[tid] = bias[tid];
    ull acc2[32];
#pragma unroll
    for (int i = 0; i < 32; i++) acc2[i] = 0ull;
    const float* wt = (STAGE == 1) ? g_w1t : g_w2t;
    const float* feat = branch ? fR : fL;
    for (int cin = 0; cin < CIN; cin++) {
        const float* src;
        if (STAGE == 1)
            src = (cin == 0) ? (g_m + (size_t)bz * HWSZ)
                             : (feat + ((size_t)b * CC + (cin - 1)) * HWSZ);
        else
            src = g_x1 + ((size_t)bz * 64 + cin) * HWSZ;
        for (int i = tid; i < 340; i += 256) {
            int r = i / 34, c = i % 34;
            int gy = by + r - 1, gx = bx + c - 1;
            tile[r][c] = (gy >= 0 && gy < HH && gx >= 0 && gx < WW) ? src[gy * WW + gx] : 0.f;
        }
        {
            const float4* wsrc = (const float4*)(wt + (size_t)cin * 576);
            float4* wdst = (float4*)ws;
            for (int i = tid; i < 144; i += 256) wdst[i] = wsrc[i];
        }
        __syncthreads();
        float inv[9];
#pragma unroll
        for (int ky = 0; ky < 3; ky++)
#pragma unroll
            for (int kx = 0; kx < 3; kx++)
                inv[ky * 3 + kx] = tile[ty + ky][tx + kx];
#pragma unroll
        for (int k = 0; k < 9; k++) {
            ull vv = pack2(inv[k], inv[k]);
            const ulonglong2* w4 = (const ulonglong2*)(ws + k * 64);
#pragma unroll
            for (int j = 0; j < 16; j++) {
                ulonglong2 ww = w4[j];
                fma2(acc2[2 * j + 0], vv, ww.x);
                fma2(acc2[2 * j + 1], vv, ww.y);
            }
        }
        __syncthreads();
    }
    float* outp = (STAGE == 1) ? g_x1 : g_x2;
    int pix = (by + ty) * WW + bx + tx;
#pragma unroll
    for (int j = 0; j < 32; j++) {
        float lo, hi;
        unpack2(acc2[j], lo, hi);
        float r0 = lo + bs[2 * j + 0];
        float r1 = hi + bs[2 * j + 1];
        r0 = r0 > 0.f ? r0 : 0.1f * r0;
        r1 = r1 > 0.f ? r1 : 0.1f * r1;
        outp[((size_t)bz * 64 + 2 * j + 0) * HWSZ + pix] = r0;
        outp[((size_t)bz * 64 + 2 * j + 1) * HWSZ + pix] = r1;
    }
}

// ---------------- conv3 (64 -> 1) + alpha * clip + exp ----------------
__global__ __launch_bounds__(256) void conv3_kernel(const float* __restrict__ w3,
                                                    const float* __restrict__ b3,
                                                    const float* __restrict__ alpha) {
    __shared__ float tile[10][34];
    __shared__ float ws[576];
    int bz = blockIdx.z;
    int bx = blockIdx.x * 32, by = blockIdx.y * 8;
    int tx = threadIdx.x, ty = threadIdx.y;
    int tid = ty * 32 + tx;
    for (int i = tid; i < 576; i += 256) ws[i] = w3[i];
    float acc = 0.f;
    for (int cin = 0; cin < 64; cin++) {
        const float* src = g_x2 + ((size_t)bz * 64 + cin) * HWSZ;
        for (int i = tid; i < 340; i += 256) {
            int r = i / 34, c = i % 34;
            int gy = by + r - 1, gx = bx + c - 1;
            tile[r][c] = (gy >= 0 && gy < HH && gx >= 0 && gx < WW) ? src[gy * WW + gx] : 0.f;
        }
        __syncthreads();
#pragma unroll
        for (int ky = 0; ky < 3; ky++)
#pragma unroll
            for (int kx = 0; kx < 3; kx++)
                acc += tile[ty + ky][tx + kx] * ws[cin * 9 + ky * 3 + kx];
        __syncthreads();
    }
    float v = alpha[0] * (acc + b3[0]);
    v = fminf(fmaxf(v, -20.f), 20.f);
    g_em[(size_t)bz * HWSZ + (by + ty) * WW + bx + tx] = expf(v);
}

// ---------------- clear splat accumulators ----------------
__global__ void clear_kernel() {
    size_t i = (size_t)blockIdx.x * blockDim.x + threadIdx.x;
    size_t n = (size_t)2 * BB * HWSZ * CP / 4;
    if (i < n) ((float4*)g_acc)[i] = make_float4(0.f, 0.f, 0.f, 0.f);
}

// ---------------- softmax splat: thread-per-pixel, NHWC accum, vec4 red atomics -------
__device__ __forceinline__ void red_add_v4(float* p, float a, float b, float c, float d) {
    asm volatile("red.global.add.v4.f32 [%0], {%1, %2, %3, %4};"
                 :: "l"(p), "f"(a), "f"(b), "f"(c), "f"(d) : "memory");
}

__global__ __launch_bounds__(256) void splat_kernel(const float* __restrict__ biflow,
                                                    const float* __restrict__ fL,
                                                    const float* __restrict__ fR) {
    int pix = blockIdx.x * blockDim.x + threadIdx.x;
    int branch = blockIdx.y >> 1;
    int b = blockIdx.y & 1;
    int x = pix & (WW - 1), y = pix >> 8;
    const float* bf = biflow + ((size_t)b * 4 + branch * 2) * HWSZ + pix;
    float tx = (float)x + bf[0] * 0.125f;
    float ty = (float)y + bf[HWSZ] * 0.125f;
    float x0f = floorf(tx), y0f = floorf(ty);
    float ax = tx - x0f, ay = ty - y0f;
    int x0 = (int)x0f, y0 = (int)y0f;
    float w[4] = {(1.f - ax) * (1.f - ay), ax * (1.f - ay), (1.f - ax) * ay, ax * ay};
    bool ok[4];
    size_t noff[4];
    int nvalid = 0;
#pragma unroll
    for (int i = 0; i < 4; i++) {
        int xi = x0 + (i & 1), yi = y0 + (i >> 1);
        ok[i] = (xi >= 0 && xi < WW && yi >= 0 && yi < HH) && (w[i] != 0.f);
        noff[i] = (size_t)(yi * WW + xi) * CP;
        nvalid += ok[i];
    }
    float m = g_em[(size_t)(branch * BB + b) * HWSZ + pix];
    const float* feat = (branch == 0 ? fL : fR) + (size_t)b * CC * HWSZ + pix;
    float* accb = g_acc + (size_t)(branch * BB + b) * HWSZ * CP;
    if (nvalid) {
#pragma unroll 4
        for (int g = 0; g < 24; g++) {
            float v0 = feat[(size_t)(4 * g + 0) * HWSZ] * m;
            float v1 = feat[(size_t)(4 * g + 1) * HWSZ] * m;
            float v2 = feat[(size_t)(4 * g + 2) * HWSZ] * m;
            float v3 = feat[(size_t)(4 * g + 3) * HWSZ] * m;
#pragma unroll
            for (int i = 0; i < 4; i++)
                if (ok[i])
                    red_add_v4(accb + noff[i] + 4 * g,
                               v0 * w[i], v1 * w[i], v2 * w[i], v3 * w[i]);
        }
#pragma unroll
        for (int i = 0; i < 4; i++)
            if (ok[i]) atomicAdd(accb + noff[i] + 96, m * w[i]);
    }
}

// ---------------- normalize + NHWC -> NCHW transpose ----------------
__global__ __launch_bounds__(256) void normalize_kernel(float* __restrict__ outWL,
                                                        float* __restrict__ outWR) {
    __shared__ float s[32 * CP];
    int bz = blockIdx.y;            // 0..3 : branch*2 + b
    int branch = bz >> 1, b = bz & 1;
    int pix0 = blockIdx.x * 32;
    int tid = threadIdx.x;
    const float* base = g_acc + ((size_t)bz * HWSZ + pix0) * CP;
    for (int i = tid; i < 32 * CP; i += 256) s[i] = base[i];
    __syncthreads();
    float* out = (branch == 0 ? outWL : outWR) + (size_t)b * CC * HWSZ + pix0;
    int tx = tid & 31;
    float inv = 1.f / (s[tx * CP + 96] + 1e-7f);
    for (int c = tid >> 5; c < CC; c += 8)
        out[(size_t)c * HWSZ + tx] = s[tx * CP + c] * inv;
}

// ---------------- 9x9 correlation, channel-pair f32x2, leaky 0.1 ----------------
__global__ __launch_bounds__(256, 1) void corr_kernel(const float* __restrict__ wl,
                                                      const float* __restrict__ wr,
                                                      float* __restrict__ cost) {
    __shared__ ull Ltp[4][8][32];     // channel pairs of L tile
    __shared__ ull Rtp[4][16][40];    // channel pairs of padded R tile
    int b = blockIdx.z;
    int bx = blockIdx.x * 32, by = blockIdx.y * 8;
    int tx = threadIdx.x, ty = threadIdx.y;
    int tid = ty * 32 + tx;
    ull acc2[81];
#pragma unroll
    for (int d = 0; d < 81; d++) acc2[d] = 0ull;
    for (int ch0 = 0; ch0 < CC; ch0 += 8) {
        // stage L pairs: 4 pair-planes x 8 x 32 = 1024 entries
        for (int i = tid; i < 1024; i += 256) {
            int p = i >> 8, rem = i & 255;
            int r = rem >> 5, c = rem & 31;
            const float* s0 = wl + ((size_t)b * CC + ch0 + 2 * p) * HWSZ + (by + r) * WW + bx + c;
            Ltp[p][r][c] = pack2(s0[0], s0[HWSZ]);
        }
        // stage R pairs with 4-halo: 4 x 16 x 40 = 2560 entries
        for (int i = tid; i < 2560; i += 256) {
            int p = i / 640, rem = i % 640;
            int r = rem / 40, c = rem % 40;
            int gy = by + r - 4, gx = bx + c - 4;
            float a = 0.f, bb2 = 0.f;
            if (gy >= 0 && gy < HH && gx >= 0 && gx < WW) {
                const float* s0 = wr + ((size_t)b * CC + ch0 + 2 * p) * HWSZ + gy * WW + gx;
                a = s0[0]; bb2 = s0[HWSZ];
            }
            Rtp[p][r][c] = pack2(a, bb2);
        }
        __syncthreads();
#pragma unroll
        for (int p = 0; p < 4; p++) {
            ull vv = Ltp[p][ty][tx];
#pragma unroll
            for (int dy = 0; dy < 9; dy++)
#pragma unroll
                for (int dx = 0; dx < 9; dx++)
                    fma2(acc2[dy * 9 + dx], vv, Rtp[p][ty + dy][tx + dx]);
        }
        __syncthreads();
    }
    int pix = (by + ty) * WW + bx + tx;
#pragma unroll
    for (int d = 0; d < 81; d++) {
        float lo, hi;
        unpack2(acc2[d], lo, hi);
        float r = (lo + hi) * (1.f / 96.f);
        r = r > 0.f ? r : 0.1f * r;
        cost[((size_t)b * 81 + d) * HWSZ + pix] = r;
    }
}

// ---------------- launch ----------------
extern "C" void kernel_launch(void* const* d_in, const int* in_sizes, int n_in,
                              void* d_out, int out_size) {
    const float* biflow = (const float*)d_in[0];
    const float* fL     = (const float*)d_in[1];
    const float* fR     = (const float*)d_in[2];
    const float* alpha  = (const float*)d_in[3];
    const float* w1     = (const float*)d_in[4];
    const float* b1     = (const float*)d_in[5];
    const float* w2     = (const float*)d_in[6];
    const float* b2     = (const float*)d_in[7];
    const float* w3     = (const float*)d_in[8];
    const float* b3     = (const float*)d_in[9];
    float* out   = (float*)d_out;
    float* outWL = out;
    float* outWR = out + (size_t)BB * CC * HWSZ;
    float* outC  = out + (size_t)2 * BB * CC * HWSZ;

    transpose_w1_kernel<<<(97 * 576 + 255) / 256, 256>>>(w1);
    transpose_w2_kernel<<<(64 * 576 + 255) / 256, 256>>>(w2);

    size_t nclr = (size_t)2 * BB * HWSZ * CP / 4;
    clear_kernel<<<(unsigned)((nclr + 255) / 256), 256>>>();

    dim3 g1(HWSZ / 256, BB, 2);
    warp_metric_kernel<<<g1, 256>>>(biflow, fL, fR);

    dim3 cblk(32, 8), cgrd(WW / 32, HH / 8, 2 * BB);
    conv_kernel<97, 1><<<cgrd, cblk>>>(fL, fR, b1);
    conv_kernel<64, 2><<<cgrd, cblk>>>(fL, fR, b2);
    conv3_kernel<<<cgrd, cblk>>>(w3, b3, alpha);

    dim3 gs(HWSZ / 256, 2 * BB);
    splat_kernel<<<gs, 256>>>(biflow, fL, fR);

    dim3 gn(HWSZ / 32, 2 * BB);
    normalize_kernel<<<gn, 256>>>(outWL, outWR);

    dim3 ggrd(WW / 32, HH / 8, BB);
    corr_kernel<<<ggrd, cblk>>>(outWL, outWR, outC);
}